// round 2
// baseline (speedup 1.0000x reference)
#include <cuda_runtime.h>
#include <math.h>

// Attend: out = softmax(Q K^T * D^-0.5) V,  B=2 H=16 S=2048 D=64, fp32.
// Flash-attention, register-tiled, packed f32x2 FFMA (Blackwell FFMA2).

#define BR 128
#define BC 64
#define DH 64
#define NTHREADS 256
#define S_LEN 2048
#define NBH 32

// smem layout (bytes):
//  QT : float[64][128]  transposed Q (scaled)      32768
//  KT2: u64 [64][34]    K pair-transposed (f32x2)  17408
//  Vs : float[64][64]   natural V                  16384
//  PT : float[64][133]  transposed P               34048
#define QT_OFF  0
#define KT2_OFF 32768
#define VS_OFF  (KT2_OFF + 17408)
#define PT_OFF  (VS_OFF + 16384)
#define SMEM_BYTES (PT_OFF + 34048)

static __device__ __forceinline__ unsigned long long dup2(float x) {
    unsigned long long r;
    asm("mov.b64 %0, {%1, %1};" : "=l"(r) : "f"(x));
    return r;
}
static __device__ __forceinline__ unsigned long long pk2(float x, float y) {
    unsigned long long r;
    asm("mov.b64 %0, {%1, %2};" : "=l"(r) : "f"(x), "f"(y));
    return r;
}
static __device__ __forceinline__ void up2(unsigned long long v, float& x, float& y) {
    asm("mov.b64 {%0, %1}, %2;" : "=f"(x), "=f"(y) : "l"(v));
}
static __device__ __forceinline__ unsigned long long ffma2(
    unsigned long long a, unsigned long long b, unsigned long long c) {
    unsigned long long d;
    asm("fma.rn.f32x2 %0, %1, %2, %3;" : "=l"(d) : "l"(a), "l"(b), "l"(c));
    return d;
}
static __device__ __forceinline__ unsigned long long fmul2(
    unsigned long long a, unsigned long long b) {
    unsigned long long d;
    asm("mul.rn.f32x2 %0, %1, %2;" : "=l"(d) : "l"(a), "l"(b));
    return d;
}

__global__ __launch_bounds__(NTHREADS, 2)
void attend_fa_kernel(const float* __restrict__ q, const float* __restrict__ k,
                      const float* __restrict__ v, float* __restrict__ out)
{
    extern __shared__ __align__(16) char smem[];
    float*              QT  = (float*)(smem + QT_OFF);
    unsigned long long* KT2 = (unsigned long long*)(smem + KT2_OFF);
    float*              Vs  = (float*)(smem + VS_OFF);
    float*              PT  = (float*)(smem + PT_OFF);

    const int tid = threadIdx.x;
    const int ty  = tid >> 4;   // 0..15 : rows 8*ty .. 8*ty+7
    const int tx  = tid & 15;   // 0..15 : cols 4*tx .. 4*tx+3
    const int qtile = blockIdx.x;   // 0..15
    const int bh    = blockIdx.y;   // 0..31

    const float scale = 0.125f;     // D^-0.5
    const size_t head_off = (size_t)bh * S_LEN * DH;
    const float4* qg      = (const float4*)(q + head_off + (size_t)qtile * BR * DH);
    const float4* kg_base = (const float4*)(k + head_off);
    const float4* vg_base = (const float4*)(v + head_off);

    // ---- load + transpose Q (pre-scaled) : QT[d][r] ----
    #pragma unroll
    for (int it = 0; it < (BR * DH / 4) / NTHREADS; ++it) {   // 8 iters
        int idx = it * NTHREADS + tid;
        int r   = idx >> 4;          // 0..127
        int c4  = idx & 15;          // float4 column
        float4 val = qg[idx];
        int d0 = c4 * 4;
        QT[(d0 + 0) * 128 + r] = val.x * scale;
        QT[(d0 + 1) * 128 + r] = val.y * scale;
        QT[(d0 + 2) * 128 + r] = val.z * scale;
        QT[(d0 + 3) * 128 + r] = val.w * scale;
    }

    float m_i[8], l_i[8];
    unsigned long long O2[8][2];
    #pragma unroll
    for (int i = 0; i < 8; ++i) {
        m_i[i] = -INFINITY; l_i[i] = 0.0f;
        O2[i][0] = 0ull; O2[i][1] = 0ull;
    }

    for (int kt = 0; kt < S_LEN / BC; ++kt) {   // 32 KV tiles
        __syncthreads();

        // ---- load K pair-transposed: KT2[d][jp] = (K[2jp][d], K[2jp+1][d]) ----
        {
            const float4* kg = kg_base + kt * BC * (DH / 4);
            #pragma unroll
            for (int it = 0; it < 2; ++it) {      // 512 items / 256 thr
                int idx = it * NTHREADS + tid;
                int jp  = idx >> 4;               // 0..31 (j-pair)
                int dq  = idx & 15;               // float4 along d
                float4 f0 = kg[(2 * jp)     * 16 + dq];
                float4 f1 = kg[(2 * jp + 1) * 16 + dq];
                int d0 = dq * 4;
                KT2[(d0 + 0) * 34 + jp] = pk2(f0.x, f1.x);
                KT2[(d0 + 1) * 34 + jp] = pk2(f0.y, f1.y);
                KT2[(d0 + 2) * 34 + jp] = pk2(f0.z, f1.z);
                KT2[(d0 + 3) * 34 + jp] = pk2(f0.w, f1.w);
            }
            // ---- load V natural (coalesced float4 copy) ----
            const float4* vg  = vg_base + kt * BC * (DH / 4);
            float4*       Vs4 = (float4*)Vs;
            #pragma unroll
            for (int it = 0; it < 4; ++it) {      // 1024 float4 / 256 thr
                int idx = it * NTHREADS + tid;
                Vs4[idx] = vg[idx];
            }
        }
        __syncthreads();

        // ---- S = Q K^T (rows 8ty.., col-pairs (4tx,4tx+1),(4tx+2,4tx+3)) ----
        unsigned long long s2[8][2];
        #pragma unroll
        for (int i = 0; i < 8; ++i) { s2[i][0] = 0ull; s2[i][1] = 0ull; }

        #pragma unroll 2
        for (int d = 0; d < DH; ++d) {
            const float4 qa = *(const float4*)&QT[d * 128 + 8 * ty];
            const float4 qb = *(const float4*)&QT[d * 128 + 8 * ty + 4];
            const ulonglong2 kb = *(const ulonglong2*)&KT2[d * 34 + 2 * tx];
            unsigned long long a[8];
            a[0] = dup2(qa.x); a[1] = dup2(qa.y); a[2] = dup2(qa.z); a[3] = dup2(qa.w);
            a[4] = dup2(qb.x); a[5] = dup2(qb.y); a[6] = dup2(qb.z); a[7] = dup2(qb.w);
            #pragma unroll
            for (int i = 0; i < 8; ++i) {
                s2[i][0] = ffma2(a[i], kb.x, s2[i][0]);
                s2[i][1] = ffma2(a[i], kb.y, s2[i][1]);
            }
        }

        // ---- online softmax (row stats replicated across the 16-lane tx group) ----
        #pragma unroll
        for (int i = 0; i < 8; ++i) {
            float p0, p1, p2, p3;
            up2(s2[i][0], p0, p1);
            up2(s2[i][1], p2, p3);
            float mx = fmaxf(fmaxf(p0, p1), fmaxf(p2, p3));
            #pragma unroll
            for (int w = 1; w < 16; w <<= 1)
                mx = fmaxf(mx, __shfl_xor_sync(0xffffffffu, mx, w));
            float mn = fmaxf(m_i[i], mx);
            float alpha = __expf(m_i[i] - mn);
            m_i[i] = mn;
            p0 = __expf(p0 - mn); p1 = __expf(p1 - mn);
            p2 = __expf(p2 - mn); p3 = __expf(p3 - mn);
            float rs = (p0 + p1) + (p2 + p3);
            #pragma unroll
            for (int w = 1; w < 16; w <<= 1)
                rs += __shfl_xor_sync(0xffffffffu, rs, w);
            l_i[i] = l_i[i] * alpha + rs;
            unsigned long long al = dup2(alpha);
            O2[i][0] = fmul2(O2[i][0], al);
            O2[i][1] = fmul2(O2[i][1], al);
            int r = 8 * ty + i;
            PT[(4 * tx + 0) * 133 + r] = p0;
            PT[(4 * tx + 1) * 133 + r] = p1;
            PT[(4 * tx + 2) * 133 + r] = p2;
            PT[(4 * tx + 3) * 133 + r] = p3;
        }
        __syncthreads();

        // ---- O += P V (cols d = 4tx..4tx+3 as two f32x2 pairs) ----
        const unsigned long long* Vs2 = (const unsigned long long*)Vs;
        #pragma unroll 4
        for (int j = 0; j < BC; ++j) {
            const float* prow = &PT[j * 133 + 8 * ty];
            const ulonglong2 vb = *(const ulonglong2*)&Vs2[j * 32 + 2 * tx];
            #pragma unroll
            for (int i = 0; i < 8; ++i) {
                unsigned long long a = dup2(prow[i]);
                O2[i][0] = ffma2(a, vb.x, O2[i][0]);
                O2[i][1] = ffma2(a, vb.y, O2[i][1]);
            }
        }
    }

    // ---- epilogue: normalize by l and store ----
    float* og = out + head_off + (size_t)qtile * BR * DH;
    #pragma unroll
    for (int i = 0; i < 8; ++i) {
        float inv = 1.0f / l_i[i];
        float o0, o1, o2, o3;
        up2(O2[i][0], o0, o1);
        up2(O2[i][1], o2, o3);
        float4 res = make_float4(o0 * inv, o1 * inv, o2 * inv, o3 * inv);
        *(float4*)&og[(8 * ty + i) * DH + 4 * tx] = res;
    }
}

extern "C" void kernel_launch(void* const* d_in, const int* in_sizes, int n_in,
                              void* d_out, int out_size)
{
    const float* q = (const float*)d_in[0];
    const float* k = (const float*)d_in[1];
    const float* v = (const float*)d_in[2];
    float* out = (float*)d_out;

    cudaFuncSetAttribute(attend_fa_kernel,
                         cudaFuncAttributeMaxDynamicSharedMemorySize, SMEM_BYTES);

    dim3 grid(S_LEN / BR, NBH);
    attend_fa_kernel<<<grid, NTHREADS, SMEM_BYTES>>>(q, k, v, out);
}

// round 4
// speedup vs baseline: 2.6925x; 2.6925x over previous
#include <cuda_runtime.h>
#include <math.h>

// Attend: out = softmax(Q K^T * D^-0.5) V,  B=2 H=16 S=2048 D=64, fp32 in/out.
// Flash attention on tensor cores: mma.sync.m16n8k8 tf32, online softmax in
// registers, P re-layout C-frag -> A-frag via warp shuffles (no smem P).

#define BR 128
#define BC 64
#define DH 64
#define NTHREADS 256
#define S_LEN 2048
#define NBH 32

#define K_LD 68   // floats per K smem row (conflict-free B-frag reads)
#define V_LD 72   // floats per V smem row

static __device__ __forceinline__ unsigned tf32(float f) {
    unsigned r;
    asm("cvt.rna.tf32.f32 %0, %1;" : "=r"(r) : "f"(f));
    return r;
}

static __device__ __forceinline__ void mma_tf32(
    float& d0, float& d1, float& d2, float& d3,
    unsigned a0, unsigned a1, unsigned a2, unsigned a3,
    unsigned b0, unsigned b1)
{
    asm volatile(
        "mma.sync.aligned.m16n8k8.row.col.f32.tf32.tf32.f32 "
        "{%0,%1,%2,%3}, {%4,%5,%6,%7}, {%8,%9}, {%0,%1,%2,%3};"
        : "+f"(d0), "+f"(d1), "+f"(d2), "+f"(d3)
        : "r"(a0), "r"(a1), "r"(a2), "r"(a3), "r"(b0), "r"(b1));
}

__global__ __launch_bounds__(NTHREADS, 2)
void attend_mma_kernel(const float* __restrict__ q, const float* __restrict__ k,
                       const float* __restrict__ v, float* __restrict__ out)
{
    __shared__ float Ks[BC * K_LD];   // K natural [j][d], padded
    __shared__ float Vs[BC * V_LD];   // V natural [j][d], padded

    const int tid  = threadIdx.x;
    const int warp = tid >> 5;
    const int lane = tid & 31;
    const int gid  = lane >> 2;   // 0..7
    const int tig  = lane & 3;    // 0..3

    const int qtile = blockIdx.x;
    const int bh    = blockIdx.y;
    const float scale = 0.125f;

    const size_t head_off = (size_t)bh * S_LEN * DH;
    const float*  qg      = q + head_off + (size_t)qtile * BR * DH;
    const float4* kg_base = (const float4*)(k + head_off);
    const float4* vg_base = (const float4*)(v + head_off);

    // ---- Q A-fragments in registers (pre-scaled, tf32), per k-step ks ----
    // aq[ks][0] = Q[r0+gid][8ks+tig], [1]=row+8, [2]=col+4, [3]=both
    const int r0 = warp * 16;
    unsigned aq[8][4];
    #pragma unroll
    for (int ks = 0; ks < 8; ++ks) {
        int c = 8 * ks + tig;
        aq[ks][0] = tf32(qg[(r0 + gid)     * DH + c]     * scale);
        aq[ks][1] = tf32(qg[(r0 + gid + 8) * DH + c]     * scale);
        aq[ks][2] = tf32(qg[(r0 + gid)     * DH + c + 4] * scale);
        aq[ks][3] = tf32(qg[(r0 + gid + 8) * DH + c + 4] * scale);
    }

    // output accumulators: o[nt][0..3], C layout (rows gid/gid+8, cols 8nt+2tig(+1))
    float o[8][4];
    #pragma unroll
    for (int nt = 0; nt < 8; ++nt)
        o[nt][0] = o[nt][1] = o[nt][2] = o[nt][3] = 0.0f;
    float m0 = -INFINITY, m1 = -INFINITY, l0 = 0.0f, l1 = 0.0f;

    const int srcA = (lane & ~3) | (tig >> 1);
    const int srcB = srcA | 2;

    for (int kt = 0; kt < S_LEN / BC; ++kt) {
        __syncthreads();
        // ---- stage K,V tiles (coalesced float4) ----
        {
            const float4* kg = kg_base + kt * BC * (DH / 4);
            const float4* vg = vg_base + kt * BC * (DH / 4);
            #pragma unroll
            for (int it = 0; it < 4; ++it) {          // 1024 float4 / 256 thr
                int idx = it * NTHREADS + tid;
                int j   = idx >> 4;
                int dq  = idx & 15;
                *(float4*)&Ks[j * K_LD + dq * 4] = kg[idx];
                *(float4*)&Vs[j * V_LD + dq * 4] = vg[idx];
            }
        }
        __syncthreads();

        // ---- S = Q K^T : sc[nt] covers cols 8nt..8nt+7 ----
        float sc[8][4];
        #pragma unroll
        for (int nt = 0; nt < 8; ++nt)
            sc[nt][0] = sc[nt][1] = sc[nt][2] = sc[nt][3] = 0.0f;

        #pragma unroll
        for (int ks = 0; ks < 8; ++ks) {
            #pragma unroll
            for (int nt = 0; nt < 8; ++nt) {
                // B[k][n] = K[8nt+n][8ks+k]; frag b0=B[tig][gid], b1=B[tig+4][gid]
                const float* kr = &Ks[(8 * nt + gid) * K_LD + 8 * ks];
                unsigned b0 = tf32(kr[tig]);
                unsigned b1 = tf32(kr[tig + 4]);
                mma_tf32(sc[nt][0], sc[nt][1], sc[nt][2], sc[nt][3],
                         aq[ks][0], aq[ks][1], aq[ks][2], aq[ks][3], b0, b1);
            }
        }

        // ---- online softmax (rows gid and gid+8) ----
        float rm0 = -INFINITY, rm1 = -INFINITY;
        #pragma unroll
        for (int nt = 0; nt < 8; ++nt) {
            rm0 = fmaxf(rm0, fmaxf(sc[nt][0], sc[nt][1]));
            rm1 = fmaxf(rm1, fmaxf(sc[nt][2], sc[nt][3]));
        }
        rm0 = fmaxf(rm0, __shfl_xor_sync(0xffffffffu, rm0, 1));
        rm0 = fmaxf(rm0, __shfl_xor_sync(0xffffffffu, rm0, 2));
        rm1 = fmaxf(rm1, __shfl_xor_sync(0xffffffffu, rm1, 1));
        rm1 = fmaxf(rm1, __shfl_xor_sync(0xffffffffu, rm1, 2));

        float mn0 = fmaxf(m0, rm0), mn1 = fmaxf(m1, rm1);
        float al0 = __expf(m0 - mn0), al1 = __expf(m1 - mn1);
        m0 = mn0; m1 = mn1;

        float rs0 = 0.0f, rs1 = 0.0f;
        #pragma unroll
        for (int nt = 0; nt < 8; ++nt) {
            sc[nt][0] = __expf(sc[nt][0] - mn0);
            sc[nt][1] = __expf(sc[nt][1] - mn0);
            sc[nt][2] = __expf(sc[nt][2] - mn1);
            sc[nt][3] = __expf(sc[nt][3] - mn1);
            rs0 += sc[nt][0] + sc[nt][1];
            rs1 += sc[nt][2] + sc[nt][3];
        }
        rs0 += __shfl_xor_sync(0xffffffffu, rs0, 1);
        rs0 += __shfl_xor_sync(0xffffffffu, rs0, 2);
        rs1 += __shfl_xor_sync(0xffffffffu, rs1, 1);
        rs1 += __shfl_xor_sync(0xffffffffu, rs1, 2);
        l0 = l0 * al0 + rs0;
        l1 = l1 * al1 + rs1;

        #pragma unroll
        for (int nt = 0; nt < 8; ++nt) {
            o[nt][0] *= al0; o[nt][1] *= al0;
            o[nt][2] *= al1; o[nt][3] *= al1;
        }

        // ---- O += P V ----
        // k-step ks uses P cols 8ks..8ks+7 == S n-tile ks (register re-layout
        // via quad shuffles: C-frag cols {2tig,2tig+1} -> A-frag cols {tig,tig+4})
        #pragma unroll
        for (int ks = 0; ks < 8; ++ks) {
            float q00 = __shfl_sync(0xffffffffu, sc[ks][0], srcA);
            float q01 = __shfl_sync(0xffffffffu, sc[ks][1], srcA);
            float q10 = __shfl_sync(0xffffffffu, sc[ks][0], srcB);
            float q11 = __shfl_sync(0xffffffffu, sc[ks][1], srcB);
            float r00 = __shfl_sync(0xffffffffu, sc[ks][2], srcA);
            float r01 = __shfl_sync(0xffffffffu, sc[ks][3], srcA);
            float r10 = __shfl_sync(0xffffffffu, sc[ks][2], srcB);
            float r11 = __shfl_sync(0xffffffffu, sc[ks][3], srcB);
            bool odd = (tig & 1);
            unsigned ap0 = tf32(odd ? q01 : q00);   // P[gid][8ks+tig]
            unsigned ap2 = tf32(odd ? q11 : q10);   // P[gid][8ks+tig+4]
            unsigned ap1 = tf32(odd ? r01 : r00);   // P[gid+8][8ks+tig]
            unsigned ap3 = tf32(odd ? r11 : r10);   // P[gid+8][8ks+tig+4]

            #pragma unroll
            for (int nt = 0; nt < 8; ++nt) {
                // B[k][n] = V[8ks+k][8nt+n]; b0=B[tig][gid], b1=B[tig+4][gid]
                unsigned b0 = tf32(Vs[(8 * ks + tig)     * V_LD + 8 * nt + gid]);
                unsigned b1 = tf32(Vs[(8 * ks + tig + 4) * V_LD + 8 * nt + gid]);
                mma_tf32(o[nt][0], o[nt][1], o[nt][2], o[nt][3],
                         ap0, ap1, ap2, ap3, b0, b1);
            }
        }
    }

    // ---- epilogue ----
    float inv0 = 1.0f / l0, inv1 = 1.0f / l1;
    float* og = out + head_off + (size_t)qtile * BR * DH;
    #pragma unroll
    for (int nt = 0; nt < 8; ++nt) {
        int c = 8 * nt + 2 * tig;
        float2 lo = make_float2(o[nt][0] * inv0, o[nt][1] * inv0);
        float2 hi = make_float2(o[nt][2] * inv1, o[nt][3] * inv1);
        *(float2*)&og[(r0 + gid)     * DH + c] = lo;
        *(float2*)&og[(r0 + gid + 8) * DH + c] = hi;
    }
}

extern "C" void kernel_launch(void* const* d_in, const int* in_sizes, int n_in,
                              void* d_out, int out_size)
{
    const float* q = (const float*)d_in[0];
    const float* k = (const float*)d_in[1];
    const float* v = (const float*)d_in[2];
    float* out = (float*)d_out;

    dim3 grid(S_LEN / BR, NBH);
    attend_mma_kernel<<<grid, NTHREADS>>>(q, k, v, out);
}

// round 7
// speedup vs baseline: 6.0691x; 2.2541x over previous
#include <cuda_runtime.h>
#include <cuda_fp16.h>
#include <math.h>

// Attend: out = softmax(Q K^T * D^-0.5) V,  B=2 H=16 S=2048 D=64, fp32 in/out.
// Flash attention, fp16 mma.m16n8k16 + ldmatrix, fp32 accum, online softmax.
// K/V staged to fp16 smem (double-buffered), P C-frag == A-frag (no shuffles).

#define BR 128
#define BC 64
#define DH 64
#define NTHREADS 256
#define S_LEN 2048
#define NBH 32

#define LDH 72   // halves per smem row (pad: stride 36 words -> conflict-free)

static __device__ __forceinline__ unsigned ph2(float x, float y) {
    half2 h = __floats2half2_rn(x, y);
    return *(unsigned*)&h;
}

static __device__ __forceinline__ void mma_f16(
    float& d0, float& d1, float& d2, float& d3,
    unsigned a0, unsigned a1, unsigned a2, unsigned a3,
    unsigned b0, unsigned b1)
{
    asm volatile(
        "mma.sync.aligned.m16n8k16.row.col.f32.f16.f16.f32 "
        "{%0,%1,%2,%3}, {%4,%5,%6,%7}, {%8,%9}, {%0,%1,%2,%3};"
        : "+f"(d0), "+f"(d1), "+f"(d2), "+f"(d3)
        : "r"(a0), "r"(a1), "r"(a2), "r"(a3), "r"(b0), "r"(b1));
}

static __device__ __forceinline__ void ldsm4(
    unsigned& r0, unsigned& r1, unsigned& r2, unsigned& r3, unsigned addr)
{
    asm volatile(
        "ldmatrix.sync.aligned.m8n8.x4.shared.b16 {%0,%1,%2,%3}, [%4];"
        : "=r"(r0), "=r"(r1), "=r"(r2), "=r"(r3) : "r"(addr));
}

static __device__ __forceinline__ void ldsm4t(
    unsigned& r0, unsigned& r1, unsigned& r2, unsigned& r3, unsigned addr)
{
    asm volatile(
        "ldmatrix.sync.aligned.m8n8.x4.trans.shared.b16 {%0,%1,%2,%3}, [%4];"
        : "=r"(r0), "=r"(r1), "=r"(r2), "=r"(r3) : "r"(addr));
}

__global__ __launch_bounds__(NTHREADS, 2)
void attend_f16_kernel(const float* __restrict__ q, const float* __restrict__ k,
                       const float* __restrict__ v, float* __restrict__ out)
{
    __shared__ __align__(16) __half Kh[2][BC * LDH];
    __shared__ __align__(16) __half Vh[2][BC * LDH];

    const int tid  = threadIdx.x;
    const int warp = tid >> 5;
    const int lane = tid & 31;
    const int gid  = lane >> 2;   // 0..7
    const int tig  = lane & 3;    // 0..3

    const int qtile = blockIdx.x;
    const int bh    = blockIdx.y;
    const float scale = 0.125f;

    const size_t head_off = (size_t)bh * S_LEN * DH;
    const float*  qg      = q + head_off + (size_t)qtile * BR * DH;
    const float4* kg_base = (const float4*)(k + head_off);
    const float4* vg_base = (const float4*)(v + head_off);

    // per-thread ldmatrix address components (halves -> bytes x2)
    const int kRow = ((lane >> 4) << 3) + (lane & 7);      // QK: row within nt-pair
    const int kCol = ((lane >> 3) & 1) * 8;                // QK: k-half select
    const int vRow = ((lane >> 3) & 1) * 8 + (lane & 7);   // PV: row within ks16
    const int vCol = ((lane >> 4) << 3);                   // PV: n-half select

    const unsigned kb0 = (unsigned)__cvta_generic_to_shared(&Kh[0][0]);
    const unsigned kb1 = (unsigned)__cvta_generic_to_shared(&Kh[1][0]);
    const unsigned vb0 = (unsigned)__cvta_generic_to_shared(&Vh[0][0]);
    const unsigned vb1 = (unsigned)__cvta_generic_to_shared(&Vh[1][0]);

    // ---- Q A-fragments (fp16, pre-scaled) : aq[ks16][0..3] ----
    const int r0 = warp * 16;
    unsigned aq[4][4];
    #pragma unroll
    for (int ks = 0; ks < 4; ++ks) {
        const float* qr = qg + (r0 + gid) * DH + 16 * ks + 2 * tig;
        float2 x0 = *(const float2*)qr;
        float2 x1 = *(const float2*)(qr + 8 * DH);
        float2 x2 = *(const float2*)(qr + 8);
        float2 x3 = *(const float2*)(qr + 8 * DH + 8);
        aq[ks][0] = ph2(x0.x * scale, x0.y * scale);
        aq[ks][1] = ph2(x1.x * scale, x1.y * scale);
        aq[ks][2] = ph2(x2.x * scale, x2.y * scale);
        aq[ks][3] = ph2(x3.x * scale, x3.y * scale);
    }

    float o[8][4];
    #pragma unroll
    for (int nt = 0; nt < 8; ++nt)
        o[nt][0] = o[nt][1] = o[nt][2] = o[nt][3] = 0.0f;
    float m0 = -INFINITY, m1 = -INFINITY, l0 = 0.0f, l1 = 0.0f;

    // staging indices: idx -> (j = idx>>4, dq = idx&15)
    const int sj  = tid >> 4;        // base j for this thread's items (with +16/iter)
    const int sdq = tid & 15;

    // ---- prologue: stage tile 0 into buffer 0 ----
    {
        const float4* kg = kg_base;
        const float4* vg = vg_base;
        #pragma unroll
        for (int it = 0; it < 4; ++it) {
            int j = sj + it * 16;
            float4 kf = kg[j * 16 + sdq];
            float4 vf = vg[j * 16 + sdq];
            half2* kp = (half2*)&Kh[0][j * LDH + sdq * 4];
            half2* vp = (half2*)&Vh[0][j * LDH + sdq * 4];
            kp[0] = __floats2half2_rn(kf.x, kf.y);
            kp[1] = __floats2half2_rn(kf.z, kf.w);
            vp[0] = __floats2half2_rn(vf.x, vf.y);
            vp[1] = __floats2half2_rn(vf.z, vf.w);
        }
    }
    __syncthreads();

    for (int kt = 0; kt < S_LEN / BC; ++kt) {
        const int cur = kt & 1;

        // ---- stage next tile into other buffer (LDG issued before compute) ----
        if (kt + 1 < S_LEN / BC) {
            const float4* kg = kg_base + (kt + 1) * BC * (DH / 4);
            const float4* vg = vg_base + (kt + 1) * BC * (DH / 4);
            __half* Kn = Kh[1 - cur];
            __half* Vn = Vh[1 - cur];
            #pragma unroll
            for (int it = 0; it < 4; ++it) {
                int j = sj + it * 16;
                float4 kf = kg[j * 16 + sdq];
                float4 vf = vg[j * 16 + sdq];
                half2* kp = (half2*)&Kn[j * LDH + sdq * 4];
                half2* vp = (half2*)&Vn[j * LDH + sdq * 4];
                kp[0] = __floats2half2_rn(kf.x, kf.y);
                kp[1] = __floats2half2_rn(kf.z, kf.w);
                vp[0] = __floats2half2_rn(vf.x, vf.y);
                vp[1] = __floats2half2_rn(vf.z, vf.w);
            }
        }

        const unsigned kbase = cur ? kb1 : kb0;
        const unsigned vbase = cur ? vb1 : vb0;

        // ---- S = Q K^T ----
        float sc[8][4];
        #pragma unroll
        for (int nt = 0; nt < 8; ++nt)
            sc[nt][0] = sc[nt][1] = sc[nt][2] = sc[nt][3] = 0.0f;

        #pragma unroll
        for (int ks = 0; ks < 4; ++ks) {
            #pragma unroll
            for (int ntp = 0; ntp < 4; ++ntp) {
                unsigned b0, b1, b2, b3;
                unsigned addr = kbase +
                    (unsigned)(((16 * ntp + kRow) * LDH + 16 * ks + kCol) * 2);
                ldsm4(b0, b1, b2, b3, addr);
                mma_f16(sc[2*ntp][0], sc[2*ntp][1], sc[2*ntp][2], sc[2*ntp][3],
                        aq[ks][0], aq[ks][1], aq[ks][2], aq[ks][3], b0, b1);
                mma_f16(sc[2*ntp+1][0], sc[2*ntp+1][1], sc[2*ntp+1][2], sc[2*ntp+1][3],
                        aq[ks][0], aq[ks][1], aq[ks][2], aq[ks][3], b2, b3);
            }
        }

        // ---- online softmax (rows gid, gid+8) ----
        float rm0 = -INFINITY, rm1 = -INFINITY;
        #pragma unroll
        for (int nt = 0; nt < 8; ++nt) {
            rm0 = fmaxf(rm0, fmaxf(sc[nt][0], sc[nt][1]));
            rm1 = fmaxf(rm1, fmaxf(sc[nt][2], sc[nt][3]));
        }
        rm0 = fmaxf(rm0, __shfl_xor_sync(0xffffffffu, rm0, 1));
        rm0 = fmaxf(rm0, __shfl_xor_sync(0xffffffffu, rm0, 2));
        rm1 = fmaxf(rm1, __shfl_xor_sync(0xffffffffu, rm1, 1));
        rm1 = fmaxf(rm1, __shfl_xor_sync(0xffffffffu, rm1, 2));

        float mn0 = fmaxf(m0, rm0), mn1 = fmaxf(m1, rm1);
        float al0 = __expf(m0 - mn0), al1 = __expf(m1 - mn1);
        m0 = mn0; m1 = mn1;

        float rs0 = 0.0f, rs1 = 0.0f;
        unsigned ap[4][4];   // PV A-frags, packed as computed
        #pragma unroll
        for (int nt = 0; nt < 8; ++nt) {
            sc[nt][0] = __expf(sc[nt][0] - mn0);
            sc[nt][1] = __expf(sc[nt][1] - mn0);
            sc[nt][2] = __expf(sc[nt][2] - mn1);
            sc[nt][3] = __expf(sc[nt][3] - mn1);
            rs0 += sc[nt][0] + sc[nt][1];
            rs1 += sc[nt][2] + sc[nt][3];
            // C-frag == fp16 A-frag layout: pack directly
            ap[nt >> 1][((nt & 1) << 1) + 0] = ph2(sc[nt][0], sc[nt][1]);
            ap[nt >> 1][((nt & 1) << 1) + 1] = ph2(sc[nt][2], sc[nt][3]);
        }
        rs0 += __shfl_xor_sync(0xffffffffu, rs0, 1);
        rs0 += __shfl_xor_sync(0xffffffffu, rs0, 2);
        rs1 += __shfl_xor_sync(0xffffffffu, rs1, 1);
        rs1 += __shfl_xor_sync(0xffffffffu, rs1, 2);
        l0 = l0 * al0 + rs0;
        l1 = l1 * al1 + rs1;

        #pragma unroll
        for (int nt = 0; nt < 8; ++nt) {
            o[nt][0] *= al0; o[nt][1] *= al0;
            o[nt][2] *= al1; o[nt][3] *= al1;
        }

        // ---- O += P V ----
        #pragma unroll
        for (int ks = 0; ks < 4; ++ks) {
            #pragma unroll
            for (int ntp = 0; ntp < 4; ++ntp) {
                unsigned b0, b1, b2, b3;
                unsigned addr = vbase +
                    (unsigned)(((16 * ks + vRow) * LDH + 16 * ntp + vCol) * 2);
                ldsm4t(b0, b1, b2, b3, addr);
                mma_f16(o[2*ntp][0], o[2*ntp][1], o[2*ntp][2], o[2*ntp][3],
                        ap[ks][0], ap[ks][1], ap[ks][2], ap[ks][3], b0, b1);
                mma_f16(o[2*ntp+1][0], o[2*ntp+1][1], o[2*ntp+1][2], o[2*ntp+1][3],
                        ap[ks][0], ap[ks][1], ap[ks][2], ap[ks][3], b2, b3);
            }
        }

        __syncthreads();
    }

    // ---- epilogue ----
    float inv0 = 1.0f / l0, inv1 = 1.0f / l1;
    float* og = out + head_off + (size_t)qtile * BR * DH;
    #pragma unroll
    for (int nt = 0; nt < 8; ++nt) {
        int c = 8 * nt + 2 * tig;
        float2 lo = make_float2(o[nt][0] * inv0, o[nt][1] * inv0);
        float2 hi = make_float2(o[nt][2] * inv1, o[nt][3] * inv1);
        *(float2*)&og[(r0 + gid)     * DH + c] = lo;
        *(float2*)&og[(r0 + gid + 8) * DH + c] = hi;
    }
}

extern "C" void kernel_launch(void* const* d_in, const int* in_sizes, int n_in,
                              void* d_out, int out_size)
{
    const float* q = (const float*)d_in[0];
    const float* k = (const float*)d_in[1];
    const float* v = (const float*)d_in[2];
    float* out = (float*)d_out;

    dim3 grid(S_LEN / BR, NBH);
    attend_f16_kernel<<<grid, NTHREADS>>>(q, k, v, out);
}

// round 8
// speedup vs baseline: 7.3835x; 1.2166x over previous
#include <cuda_runtime.h>
#include <cuda_fp16.h>
#include <math.h>

// Attend: out = softmax(Q K^T * D^-0.5) V,  B=2 H=16 S=2048 D=64, fp32 in/out.
// Round 8: pre-converted fp16 K/V in global scratch, cp.async 3-stage pipeline,
// fp16 mma.m16n8k16 + ldmatrix, online softmax in exp2 domain.

#define BR 128
#define BC 64
#define DH 64
#define NTHREADS 256
#define S_LEN 2048
#define NBH 32
#define NT (S_LEN / BC)

#define LDH 72                         // halves per smem row (pad)
#define KBYTES (BC * LDH * 2)          // 9216 B per K tile
#define STAGE_BYTES (2 * KBYTES)       // K + V per stage
#define NSTAGE 3
#define SMEM_BYTES (NSTAGE * STAGE_BYTES)   // 55296

#define N_ELEM (2 * 16 * 2048 * 64)

__device__ __half KH_G[N_ELEM];
__device__ __half VH_G[N_ELEM];

static __device__ __forceinline__ unsigned ph2(float x, float y) {
    half2 h = __floats2half2_rn(x, y);
    return *(unsigned*)&h;
}
static __device__ __forceinline__ float ex2(float x) {
    float r;
    asm("ex2.approx.f32 %0, %1;" : "=f"(r) : "f"(x));
    return r;
}
static __device__ __forceinline__ void mma_f16(
    float& d0, float& d1, float& d2, float& d3,
    unsigned a0, unsigned a1, unsigned a2, unsigned a3,
    unsigned b0, unsigned b1)
{
    asm volatile(
        "mma.sync.aligned.m16n8k16.row.col.f32.f16.f16.f32 "
        "{%0,%1,%2,%3}, {%4,%5,%6,%7}, {%8,%9}, {%0,%1,%2,%3};"
        : "+f"(d0), "+f"(d1), "+f"(d2), "+f"(d3)
        : "r"(a0), "r"(a1), "r"(a2), "r"(a3), "r"(b0), "r"(b1));
}
static __device__ __forceinline__ void ldsm4(
    unsigned& r0, unsigned& r1, unsigned& r2, unsigned& r3, unsigned addr)
{
    asm volatile(
        "ldmatrix.sync.aligned.m8n8.x4.shared.b16 {%0,%1,%2,%3}, [%4];"
        : "=r"(r0), "=r"(r1), "=r"(r2), "=r"(r3) : "r"(addr));
}
static __device__ __forceinline__ void ldsm4t(
    unsigned& r0, unsigned& r1, unsigned& r2, unsigned& r3, unsigned addr)
{
    asm volatile(
        "ldmatrix.sync.aligned.m8n8.x4.trans.shared.b16 {%0,%1,%2,%3}, [%4];"
        : "=r"(r0), "=r"(r1), "=r"(r2), "=r"(r3) : "r"(addr));
}
static __device__ __forceinline__ void cp16(unsigned dst, const void* src) {
    asm volatile("cp.async.cg.shared.global [%0], [%1], 16;"
                 :: "r"(dst), "l"(src));
}

// ---- preprocess: fp32 K,V -> fp16 global scratch ----
__global__ void cvt_kv_kernel(const float4* __restrict__ k,
                              const float4* __restrict__ v)
{
    int i = blockIdx.x * blockDim.x + threadIdx.x;   // over N_ELEM/4
    float4 kf = k[i];
    float4 vf = v[i];
    half2* kp = (half2*)KH_G + 2 * i;
    half2* vp = (half2*)VH_G + 2 * i;
    kp[0] = __floats2half2_rn(kf.x, kf.y);
    kp[1] = __floats2half2_rn(kf.z, kf.w);
    vp[0] = __floats2half2_rn(vf.x, vf.y);
    vp[1] = __floats2half2_rn(vf.z, vf.w);
}

__global__ __launch_bounds__(NTHREADS, 2)
void attend_f16_kernel(const float* __restrict__ q, float* __restrict__ out)
{
    extern __shared__ __align__(16) char smem[];
    const unsigned sbase = (unsigned)__cvta_generic_to_shared(smem);

    const int tid  = threadIdx.x;
    const int warp = tid >> 5;
    const int lane = tid & 31;
    const int gid  = lane >> 2;
    const int tig  = lane & 3;

    const int qtile = blockIdx.x;
    const int bh    = blockIdx.y;
    const float scale = 0.125f * 1.4426950408889634f;   // D^-0.5 * log2(e)

    const size_t head_off = (size_t)bh * S_LEN * DH;
    const float*  qg = q + head_off + (size_t)qtile * BR * DH;
    const __half* kg = KH_G + head_off;
    const __half* vg = VH_G + head_off;

    // ldmatrix per-thread address components
    const int kRow = ((lane >> 4) << 3) + (lane & 7);
    const int kCol = ((lane >> 3) & 1) * 8;
    const int vRow = ((lane >> 3) & 1) * 8 + (lane & 7);
    const int vCol = ((lane >> 4) << 3);

    // cp.async chunk mapping: 512 16B-chunks per array, 2 per thread
    const int cj0 = tid >> 3;          // row for chunk tid
    const int cc0 = tid & 7;           // 16B chunk within row

    // ---- stage tiles 0,1 (prefetch) ----
    #pragma unroll
    for (int pre = 0; pre < 2; ++pre) {
        unsigned kb = sbase + pre * STAGE_BYTES;
        unsigned vb = kb + KBYTES;
        const __half* kt_ = kg + pre * BC * DH;
        const __half* vt_ = vg + pre * BC * DH;
        #pragma unroll
        for (int it = 0; it < 2; ++it) {
            int j = cj0 + it * 32;
            unsigned so = (unsigned)((j * LDH + cc0 * 8) * 2);
            cp16(kb + so, kt_ + j * DH + cc0 * 8);
            cp16(vb + so, vt_ + j * DH + cc0 * 8);
        }
        asm volatile("cp.async.commit_group;");
    }

    // ---- Q A-fragments (fp16, pre-scaled) ----
    const int r0 = warp * 16;
    unsigned aq[4][4];
    #pragma unroll
    for (int ks = 0; ks < 4; ++ks) {
        const float* qr = qg + (r0 + gid) * DH + 16 * ks + 2 * tig;
        float2 x0 = *(const float2*)qr;
        float2 x1 = *(const float2*)(qr + 8 * DH);
        float2 x2 = *(const float2*)(qr + 8);
        float2 x3 = *(const float2*)(qr + 8 * DH + 8);
        aq[ks][0] = ph2(x0.x * scale, x0.y * scale);
        aq[ks][1] = ph2(x1.x * scale, x1.y * scale);
        aq[ks][2] = ph2(x2.x * scale, x2.y * scale);
        aq[ks][3] = ph2(x3.x * scale, x3.y * scale);
    }

    float o[8][4];
    #pragma unroll
    for (int nt = 0; nt < 8; ++nt)
        o[nt][0] = o[nt][1] = o[nt][2] = o[nt][3] = 0.0f;
    float m0 = -INFINITY, m1 = -INFINITY, l0 = 0.0f, l1 = 0.0f;

    int st = 0;
    for (int kt = 0; kt < NT; ++kt) {
        asm volatile("cp.async.wait_group 1;");
        __syncthreads();

        const unsigned kbase = sbase + st * STAGE_BYTES;
        const unsigned vbase = kbase + KBYTES;

        // ---- S = Q K^T ----
        float sc[8][4];
        #pragma unroll
        for (int nt = 0; nt < 8; ++nt)
            sc[nt][0] = sc[nt][1] = sc[nt][2] = sc[nt][3] = 0.0f;

        #pragma unroll
        for (int ks = 0; ks < 4; ++ks) {
            #pragma unroll
            for (int ntp = 0; ntp < 4; ++ntp) {
                unsigned b0, b1, b2, b3;
                unsigned addr = kbase +
                    (unsigned)(((16 * ntp + kRow) * LDH + 16 * ks + kCol) * 2);
                ldsm4(b0, b1, b2, b3, addr);
                mma_f16(sc[2*ntp][0], sc[2*ntp][1], sc[2*ntp][2], sc[2*ntp][3],
                        aq[ks][0], aq[ks][1], aq[ks][2], aq[ks][3], b0, b1);
                mma_f16(sc[2*ntp+1][0], sc[2*ntp+1][1], sc[2*ntp+1][2], sc[2*ntp+1][3],
                        aq[ks][0], aq[ks][1], aq[ks][2], aq[ks][3], b2, b3);
            }
        }

        // ---- online softmax (base-2 domain) ----
        float rm0 = -INFINITY, rm1 = -INFINITY;
        #pragma unroll
        for (int nt = 0; nt < 8; ++nt) {
            rm0 = fmaxf(rm0, fmaxf(sc[nt][0], sc[nt][1]));
            rm1 = fmaxf(rm1, fmaxf(sc[nt][2], sc[nt][3]));
        }
        rm0 = fmaxf(rm0, __shfl_xor_sync(0xffffffffu, rm0, 1));
        rm0 = fmaxf(rm0, __shfl_xor_sync(0xffffffffu, rm0, 2));
        rm1 = fmaxf(rm1, __shfl_xor_sync(0xffffffffu, rm1, 1));
        rm1 = fmaxf(rm1, __shfl_xor_sync(0xffffffffu, rm1, 2));

        float mn0 = fmaxf(m0, rm0), mn1 = fmaxf(m1, rm1);
        float al0 = ex2(m0 - mn0), al1 = ex2(m1 - mn1);
        m0 = mn0; m1 = mn1;

        float rs0 = 0.0f, rs1 = 0.0f;
        unsigned ap[4][4];
        #pragma unroll
        for (int nt = 0; nt < 8; ++nt) {
            sc[nt][0] = ex2(sc[nt][0] - mn0);
            sc[nt][1] = ex2(sc[nt][1] - mn0);
            sc[nt][2] = ex2(sc[nt][2] - mn1);
            sc[nt][3] = ex2(sc[nt][3] - mn1);
            rs0 += sc[nt][0] + sc[nt][1];
            rs1 += sc[nt][2] + sc[nt][3];
            ap[nt >> 1][((nt & 1) << 1) + 0] = ph2(sc[nt][0], sc[nt][1]);
            ap[nt >> 1][((nt & 1) << 1) + 1] = ph2(sc[nt][2], sc[nt][3]);
        }
        rs0 += __shfl_xor_sync(0xffffffffu, rs0, 1);
        rs0 += __shfl_xor_sync(0xffffffffu, rs0, 2);
        rs1 += __shfl_xor_sync(0xffffffffu, rs1, 1);
        rs1 += __shfl_xor_sync(0xffffffffu, rs1, 2);
        l0 = l0 * al0 + rs0;
        l1 = l1 * al1 + rs1;

        #pragma unroll
        for (int nt = 0; nt < 8; ++nt) {
            o[nt][0] *= al0; o[nt][1] *= al0;
            o[nt][2] *= al1; o[nt][3] *= al1;
        }

        // ---- O += P V ----
        #pragma unroll
        for (int ks = 0; ks < 4; ++ks) {
            #pragma unroll
            for (int ntp = 0; ntp < 4; ++ntp) {
                unsigned b0, b1, b2, b3;
                unsigned addr = vbase +
                    (unsigned)(((16 * ks + vRow) * LDH + 16 * ntp + vCol) * 2);
                ldsm4t(b0, b1, b2, b3, addr);
                mma_f16(o[2*ntp][0], o[2*ntp][1], o[2*ntp][2], o[2*ntp][3],
                        ap[ks][0], ap[ks][1], ap[ks][2], ap[ks][3], b0, b1);
                mma_f16(o[2*ntp+1][0], o[2*ntp+1][1], o[2*ntp+1][2], o[2*ntp+1][3],
                        ap[ks][0], ap[ks][1], ap[ks][2], ap[ks][3], b2, b3);
            }
        }

        // ---- stage tile kt+2, always commit (keeps group accounting exact) ----
        if (kt + 2 < NT) {
            int st2 = st + 2; if (st2 >= NSTAGE) st2 -= NSTAGE;
            unsigned kb = sbase + st2 * STAGE_BYTES;
            unsigned vb = kb + KBYTES;
            const __half* kt_ = kg + (kt + 2) * BC * DH;
            const __half* vt_ = vg + (kt + 2) * BC * DH;
            #pragma unroll
            for (int it = 0; it < 2; ++it) {
                int j = cj0 + it * 32;
                unsigned so = (unsigned)((j * LDH + cc0 * 8) * 2);
                cp16(kb + so, kt_ + j * DH + cc0 * 8);
                cp16(vb + so, vt_ + j * DH + cc0 * 8);
            }
        }
        asm volatile("cp.async.commit_group;");

        st = (st == NSTAGE - 1) ? 0 : st + 1;
    }

    // ---- epilogue ----
    float inv0 = 1.0f / l0, inv1 = 1.0f / l1;
    float* og = out + head_off + (size_t)qtile * BR * DH;
    #pragma unroll
    for (int nt = 0; nt < 8; ++nt) {
        int c = 8 * nt + 2 * tig;
        float2 lo = make_float2(o[nt][0] * inv0, o[nt][1] * inv0);
        float2 hi = make_float2(o[nt][2] * inv1, o[nt][3] * inv1);
        *(float2*)&og[(r0 + gid)     * DH + c] = lo;
        *(float2*)&og[(r0 + gid + 8) * DH + c] = hi;
    }
}

extern "C" void kernel_launch(void* const* d_in, const int* in_sizes, int n_in,
                              void* d_out, int out_size)
{
    const float* q = (const float*)d_in[0];
    const float* k = (const float*)d_in[1];
    const float* v = (const float*)d_in[2];
    float* out = (float*)d_out;

    cudaFuncSetAttribute(attend_f16_kernel,
                         cudaFuncAttributeMaxDynamicSharedMemorySize, SMEM_BYTES);

    cvt_kv_kernel<<<N_ELEM / 4 / 256, 256>>>((const float4*)k, (const float4*)v);

    dim3 grid(S_LEN / BR, NBH);
    attend_f16_kernel<<<grid, NTHREADS, SMEM_BYTES>>>(q, out);
}